// round 7
// baseline (speedup 1.0000x reference)
#include <cuda_runtime.h>
#include <cuda_bf16.h>
#include <math.h>

// ArcFace-style margin softmax cross-entropy loss (fused single kernel).
//   loss = mean_b [ logsumexp_c(logits[b,c]) - logits[b, label_b] ]
// logits = clip(cos,-1+eps,1-eps)*64; label column replaced by
// (ct*cos(m) - sqrt(1-ct^2)*sin(m))*64.
//
// Single pass, fixed-shift logsumexp (shift = 64 = max possible logit).
// exp(64x-64) = ex2(x*92.33248 - 92.33248) (log2e folded in).
//
// This round: 2 rows per CTA, interleaved in one load loop (grid = B/2).
// Rationale: DRAM streams at ~spec when active but sits idle ~25% of the
// kernel (wave transitions + synchronized epilogues). Halving CTA count
// cuts waves 3.46->1.73 and halves sync points per byte; dual row streams
// double per-thread MLP. Per-SM balance stays ~2%.

#define EPS_CLIP 1e-7f
#define SCALE 64.0f
#define L2E_SCALE 92.33248262f   // 64 * log2(e)
#define TPB 256

static __device__ float g_row_loss[4096];          // per-row losses (B <= 4096)
static __device__ unsigned int g_done_count = 0;   // reset to 0 by last block

__device__ __forceinline__ float clipf(float x) {
    return fminf(fmaxf(x, -1.0f + EPS_CLIP), 1.0f - EPS_CLIP);
}

__device__ __forceinline__ float ex2_approx(float t) {
    float r;
    asm("ex2.approx.ftz.f32 %0, %1;" : "=f"(r) : "f"(t));
    return r;
}

// exp(clip(x)*64 - 64)
__device__ __forceinline__ float term(float x) {
    return ex2_approx(fmaf(clipf(x), L2E_SCALE, -L2E_SCALE));
}

__device__ __forceinline__ float warp_reduce(float v) {
    #pragma unroll
    for (int off = 16; off > 0; off >>= 1)
        v += __shfl_xor_sync(0xffffffffu, v, off);
    return v;
}

// computes row loss given the full-row exp-sum (shift 64)
__device__ __forceinline__ float row_loss(
    const float* cos_theta, const int* labels, const float* margins,
    int row, int C, float s)
{
    int lab = labels[row];
    float cl = clipf(cos_theta[(size_t)row * (size_t)C + (size_t)lab]);
    float m = margins[lab];
    float cm = cosf(m);
    float sm = sinf(m);
    float sin_l = sqrtf(fmaxf(1.0f - cl * cl, 0.0f));
    float target = cl * cm - sin_l * sm;        // cos(theta + m)
    float target_logit = target * SCALE;
    // swap label-column contribution (term() form cancels exactly)
    float sum = s
              + ex2_approx(fmaf(target, L2E_SCALE, -L2E_SCALE))
              - term(cl);
    return (SCALE + logf(sum)) - target_logit;
}

__global__ void __launch_bounds__(TPB) margin_loss_2row_kernel(
    const float* __restrict__ cos_theta,
    const int* __restrict__ labels,
    const float* __restrict__ margins,
    float* __restrict__ out,
    int B, int C, int nPair)
{
    const int r0 = blockIdx.x;
    const int r1 = blockIdx.x + nPair;
    const bool has1 = (r1 < B);
    const int tid = threadIdx.x;
    const int lane = tid & 31;
    const int wid = tid >> 5;

    const size_t off0 = (size_t)r0 * (size_t)C;
    const size_t off1 = (size_t)(has1 ? r1 : r0) * (size_t)C;  // safe alias if odd B
    const float4* p0 = reinterpret_cast<const float4*>(cos_theta + off0);
    const float4* p1 = reinterpret_cast<const float4*>(cos_theta + off1);
    const int n4 = C >> 2;

    // two interleaved row streams -> 2 independent loads in flight per thread
    float a0 = 0.0f, a1 = 0.0f;
    for (int i = tid; i < n4; i += TPB) {
        float4 v0 = p0[i];
        float4 v1 = p1[i];
        a0 += term(v0.x) + term(v0.y) + term(v0.z) + term(v0.w);
        a1 += term(v1.x) + term(v1.y) + term(v1.z) + term(v1.w);
    }
    // scalar tail (C % 4)
    for (int i = (n4 << 2) + tid; i < C; i += TPB) {
        a0 += term(cos_theta[off0 + i]);
        a1 += term(cos_theta[off1 + i]);
    }

    a0 = warp_reduce(a0);
    a1 = warp_reduce(a1);

    __shared__ float warp_sum0[TPB / 32];
    __shared__ float warp_sum1[TPB / 32];
    if (lane == 0) { warp_sum0[wid] = a0; warp_sum1[wid] = a1; }
    __syncthreads();   // warps 1..7 retire after this

    if (wid == 0) {
        float s0 = (lane < TPB / 32) ? warp_sum0[lane] : 0.0f;
        float s1 = (lane < TPB / 32) ? warp_sum1[lane] : 0.0f;
        #pragma unroll
        for (int off = 4; off > 0; off >>= 1) {
            s0 += __shfl_xor_sync(0xffffffffu, s0, off);
            s1 += __shfl_xor_sync(0xffffffffu, s1, off);
        }

        unsigned int is_last = 0;
        if (lane == 0) {
            g_row_loss[r0] = row_loss(cos_theta, labels, margins, r0, C, s0);
            if (has1)
                g_row_loss[r1] = row_loss(cos_theta, labels, margins, r1, C, s1);

            __threadfence();
            unsigned int prev = atomicAdd(&g_done_count, 1u);
            is_last = (prev == (unsigned int)(gridDim.x - 1)) ? 1u : 0u;
        }
        is_last = __shfl_sync(0xffffffffu, is_last, 0);

        if (is_last) {
            __threadfence();  // acquire side of the producer fences
            float r = 0.0f;
            for (int j = lane; j < B; j += 32)
                r += __ldcg(&g_row_loss[j]);
            r = warp_reduce(r);
            if (lane == 0) {
                out[0] = r / (float)B;
                g_done_count = 0;   // reset for next graph replay
            }
        }
    }
}

extern "C" void kernel_launch(void* const* d_in, const int* in_sizes, int n_in,
                              void* d_out, int out_size)
{
    const float* cos_theta = (const float*)d_in[0];
    const int*   labels    = (const int*)d_in[1];
    const float* margins   = (const float*)d_in[2];
    float* out = (float*)d_out;

    const int B = in_sizes[1];
    const int C = in_sizes[0] / B;
    const int nPair = (B + 1) / 2;

    margin_loss_2row_kernel<<<nPair, TPB>>>(cos_theta, labels, margins, out, B, C, nPair);
}

// round 8
// speedup vs baseline: 1.0379x; 1.0379x over previous
#include <cuda_runtime.h>
#include <cuda_bf16.h>
#include <math.h>

// ArcFace-style margin softmax cross-entropy loss — two kernels + PDL.
//   loss = mean_b [ logsumexp_c(logits[b,c]) - logits[b, label_b] ]
// logits = clip(cos,-1+eps,1-eps)*64; label column replaced by
// (ct*cos(m) - sqrt(1-ct^2)*sin(m))*64.
//
// Kernel 1 (streaming): single pass, fixed-shift logsumexp (shift = 64),
// exp(64x-64) = ex2(x*92.33248 - 92.33248). Epilogue is a plain store of
// the per-row loss — NO fence, NO atomic (the per-CTA membar.gpu+ATOMG
// epilogue of the fused variants measurably cost ~5us of stream BW).
//
// Kernel 2 (reduce): launched with programmatic stream serialization; its
// launch prologue overlaps kernel 1. griddepcontrol.wait releases at
// primary grid completion with full memory visibility (no explicit
// launch_dependents trigger in the primary).

#define EPS_CLIP 1e-7f
#define SCALE 64.0f
#define L2E_SCALE 92.33248262f   // 64 * log2(e)
#define TPB 256

static __device__ float g_row_loss[4096];   // per-row losses (B <= 4096)

__device__ __forceinline__ float clipf(float x) {
    return fminf(fmaxf(x, -1.0f + EPS_CLIP), 1.0f - EPS_CLIP);
}

__device__ __forceinline__ float ex2_approx(float t) {
    float r;
    asm("ex2.approx.ftz.f32 %0, %1;" : "=f"(r) : "f"(t));
    return r;
}

// exp(clip(x)*64 - 64)
__device__ __forceinline__ float term(float x) {
    return ex2_approx(fmaf(clipf(x), L2E_SCALE, -L2E_SCALE));
}

__device__ __forceinline__ float warp_reduce(float v) {
    #pragma unroll
    for (int off = 16; off > 0; off >>= 1)
        v += __shfl_xor_sync(0xffffffffu, v, off);
    return v;
}

__global__ void __launch_bounds__(TPB) margin_row_kernel(
    const float* __restrict__ cos_theta,
    const int* __restrict__ labels,
    const float* __restrict__ margins,
    int C)
{
    const int row = blockIdx.x;
    const int tid = threadIdx.x;
    const int lane = tid & 31;
    const int wid = tid >> 5;
    const size_t row_off = (size_t)row * (size_t)C;
    const float4* rp = reinterpret_cast<const float4*>(cos_theta + row_off);
    const int n4 = C >> 2;

    float acc = 0.0f;
    // strided float4 loads; fixed per-thread order -> deterministic.
    for (int i = tid; i < n4; i += TPB) {
        float4 v = rp[i];
        acc += term(v.x);
        acc += term(v.y);
        acc += term(v.z);
        acc += term(v.w);
    }
    // scalar tail (C % 4)
    for (int i = (n4 << 2) + tid; i < C; i += TPB) {
        acc += term(cos_theta[row_off + i]);
    }

    acc = warp_reduce(acc);

    __shared__ float warp_sum[TPB / 32];
    if (lane == 0) warp_sum[wid] = acc;
    __syncthreads();   // warps 1..7 retire after this

    if (wid == 0) {
        float s = (lane < TPB / 32) ? warp_sum[lane] : 0.0f;
        #pragma unroll
        for (int off = 4; off > 0; off >>= 1)
            s += __shfl_xor_sync(0xffffffffu, s, off);

        if (lane == 0) {
            int lab = labels[row];
            float cl = clipf(cos_theta[row_off + (size_t)lab]);
            float m = margins[lab];
            float cm = cosf(m);
            float sm = sinf(m);
            float sin_l = sqrtf(fmaxf(1.0f - cl * cl, 0.0f));
            float target = cl * cm - sin_l * sm;      // cos(theta + m)
            float target_logit = target * SCALE;

            // swap label-column contribution (term() form cancels exactly)
            float sum = s
                      + ex2_approx(fmaf(target, L2E_SCALE, -L2E_SCALE))
                      - term(cl);

            g_row_loss[row] = (SCALE + logf(sum)) - target_logit;
        }
    }
    // plain exit — no fence, no atomic
}

__global__ void __launch_bounds__(256) final_reduce_kernel(float* __restrict__ out, int B)
{
    // Wait for the primary grid (launched with programmatic serialization).
    // No trigger in the primary -> releases at primary completion with full
    // memory visibility of g_row_loss.
    asm volatile("griddepcontrol.wait;" ::: "memory");

    const int tid = threadIdx.x;
    const int lane = tid & 31;
    const int wid = tid >> 5;

    float acc = 0.0f;
    for (int i = tid; i < B; i += 256) acc += g_row_loss[i];
    acc = warp_reduce(acc);

    __shared__ float warp_sum[8];
    if (lane == 0) warp_sum[wid] = acc;
    __syncthreads();

    if (wid == 0) {
        float s = (lane < 8) ? warp_sum[lane] : 0.0f;
        #pragma unroll
        for (int off = 4; off > 0; off >>= 1)
            s += __shfl_xor_sync(0xffffffffu, s, off);
        if (lane == 0) out[0] = s / (float)B;
    }
}

extern "C" void kernel_launch(void* const* d_in, const int* in_sizes, int n_in,
                              void* d_out, int out_size)
{
    const float* cos_theta = (const float*)d_in[0];
    const int*   labels    = (const int*)d_in[1];
    const float* margins   = (const float*)d_in[2];
    float* out = (float*)d_out;

    const int B = in_sizes[1];
    const int C = in_sizes[0] / B;

    margin_row_kernel<<<B, TPB>>>(cos_theta, labels, margins, C);

    // Secondary launch with programmatic stream serialization (PDL): its
    // launch prologue overlaps the primary's execution; griddepcontrol.wait
    // inside the kernel provides the ordering.
    cudaLaunchConfig_t cfg = {};
    cfg.gridDim  = dim3(1, 1, 1);
    cfg.blockDim = dim3(256, 1, 1);
    cfg.dynamicSmemBytes = 0;
    cfg.stream = 0;  // legacy default stream (same as <<<>>> above)
    cudaLaunchAttribute attr[1];
    attr[0].id = cudaLaunchAttributeProgrammaticStreamSerialization;
    attr[0].val.programmaticStreamSerializationAllowed = 1;
    cfg.attrs = attr;
    cfg.numAttrs = 1;
    cudaLaunchKernelEx(&cfg, final_reduce_kernel, out, B);
}